// round 11
// baseline (speedup 1.0000x reference)
#include <cuda_runtime.h>
#include <cuda_bf16.h>
#include <cstdint>

// Problem constants (fixed by the dataset)
#define NN 100000
#define EE 1600000
#define C  128           // IN_C == OUT_C == 128
#define CAP 96           // max bucket capacity per node (Poisson(16) tail ~1e-16)

// Scratch (no allocations allowed — device globals)
__device__ __nv_bfloat16 g_xbf[(size_t)NN * C];    // 25.6 MB bf16 copy of x
__device__ int   g_cnt[NN];                        // per-node degree counters
__device__ int   g_bucket[(size_t)NN * CAP];       // 38.4 MB src-id buckets
__device__ uint32_t g_wl_tf[C * C];                // W_l pre-converted to tf32 bits
__device__ uint32_t g_wr_tf[C * C];                // W_r pre-converted to tf32 bits

// ---------------------------------------------------------------------------
// Helpers
// ---------------------------------------------------------------------------
__device__ __forceinline__ uint32_t f2tf32(float f) {
    uint32_t r;
    asm("cvt.rna.tf32.f32 %0, %1;" : "=r"(r) : "f"(f));
    return r;
}

__device__ __forceinline__ void mma_tf32(float c[4], const uint32_t a[4],
                                         const uint32_t b[2]) {
    asm volatile(
        "mma.sync.aligned.m16n8k8.row.col.f32.tf32.tf32.f32 "
        "{%0,%1,%2,%3}, {%4,%5,%6,%7}, {%8,%9}, {%0,%1,%2,%3};"
        : "+f"(c[0]), "+f"(c[1]), "+f"(c[2]), "+f"(c[3])
        : "r"(a[0]), "r"(a[1]), "r"(a[2]), "r"(a[3]), "r"(b[0]), "r"(b[1]));
}

__device__ __forceinline__ void cp_async16(uint32_t smem_addr, const void* gptr) {
    asm volatile("cp.async.cg.shared.global [%0], [%1], 16;"
                 :: "r"(smem_addr), "l"(gptr));
}
__device__ __forceinline__ void cp_async_commit() {
    asm volatile("cp.async.commit_group;");
}
__device__ __forceinline__ void cp_async_wait0() {
    asm volatile("cp.async.wait_group 0;");
}

__device__ __forceinline__ void acc_bf4(float4& acc, uint2 u) {
    acc.x += __uint_as_float(u.x << 16);
    acc.y += __uint_as_float(u.x & 0xFFFF0000u);
    acc.z += __uint_as_float(u.y << 16);
    acc.w += __uint_as_float(u.y & 0xFFFF0000u);
}

// ---------------------------------------------------------------------------
// Kernel 0: convert x -> bf16, W_l/W_r -> tf32 bits; zero counters.
// ---------------------------------------------------------------------------
__global__ __launch_bounds__(256) void convert_kernel(
    const float* __restrict__ x,
    const float* __restrict__ W_l,
    const float* __restrict__ W_r)
{
    int i = blockIdx.x * blockDim.x + threadIdx.x;   // one float4 per thread
    const int n4 = NN * (C / 4);                      // 3.2M
    if (i < n4) {
        float4 v = __ldg((const float4*)x + i);
        __nv_bfloat162 h0 = __floats2bfloat162_rn(v.x, v.y);
        __nv_bfloat162 h1 = __floats2bfloat162_rn(v.z, v.w);
        uint2 u;
        u.x = *(uint32_t*)&h0;
        u.y = *(uint32_t*)&h1;
        ((uint2*)g_xbf)[i] = u;
    }
    if (i < C * C / 4) {  // 4096 float4 per weight matrix
        float4 wl = __ldg((const float4*)W_l + i);
        float4 wr = __ldg((const float4*)W_r + i);
        uint4 ul, ur;
        ul.x = f2tf32(wl.x); ul.y = f2tf32(wl.y);
        ul.z = f2tf32(wl.z); ul.w = f2tf32(wl.w);
        ur.x = f2tf32(wr.x); ur.y = f2tf32(wr.y);
        ur.z = f2tf32(wr.z); ur.w = f2tf32(wr.w);
        ((uint4*)g_wl_tf)[i] = ul;
        ((uint4*)g_wr_tf)[i] = ur;
    }
    if (i < NN) g_cnt[i] = 0;
}

// ---------------------------------------------------------------------------
// Kernel 1: bucket fill. One thread per edge.
// ---------------------------------------------------------------------------
__global__ __launch_bounds__(256) void fill_kernel(
    const int* __restrict__ edge_row,   // dst
    const int* __restrict__ edge_col)   // src
{
    int e = blockIdx.x * blockDim.x + threadIdx.x;
    if (e >= EE) return;
    int d   = __ldg(edge_row + e);
    int s   = __ldg(edge_col + e);
    int pos = atomicAdd(g_cnt + d, 1);
    if (pos < CAP) {
        g_bucket[(size_t)d * CAP + pos] = s;
    }
}

// ---------------------------------------------------------------------------
// Kernel 2: FUSED gather-aggregate + tensor-core GEMM.
//   agg = mean_{s in nbrs(r)} xbf[s]   (gathered into bf16 smem tile)
//   out = relu( agg @ W_l + x @ W_r + b_l )
//
// 256 threads (8 warps 2x4, warp tile 64x32), 128-row output tile, 2 CTAs/SM.
// Phase A (gather): each warp aggregates 16 nodes into AggBf[128][136] bf16.
// Phase B (GEMM): 8 K-chunks of 32.
//   chunks 0-3: A-frags read directly from AggBf via LDS.U16 + <<16
//               (bf16 -> tf32 bit-exact; same numerics as R10).
//   chunks 4-7: A = x fp32, register-prefetched + tf32 STS (double buffer).
//   W: cp.async from pre-converted tf32 copies (double buffer), all chunks.
// Smem: Agg 34.8KB + A 2x18.4KB + W 2x17.4KB = 106.5KB -> 2 CTAs = 213KB.
// With 2 CTAs/SM, one CTA's L2-bound gather overlaps the other's MMA phases.
// ---------------------------------------------------------------------------
#define AGG_S16  136                  // u16 stride of agg tile
#define AGG_U32  (128 * 68)           // u32 words (= 128*136 u16)
#define A_STRIDE 36
#define W_STRIDE 136
#define A_BUF    (128 * A_STRIDE)     // u32 per buffer
#define W_BUF    (32 * W_STRIDE)
#define SMEM_U32 (AGG_U32 + 2 * A_BUF + 2 * W_BUF)

__global__ __launch_bounds__(256, 2) void sage_fused_kernel(
    const float* __restrict__ x,
    const float* __restrict__ b_l,
    float*       __restrict__ out)
{
    extern __shared__ uint32_t sm[];
    uint32_t* Agg = sm;                       // bf16 agg tile (as u32 words)
    uint32_t* As  = sm + AGG_U32;             // 2 x tf32 A buffers (x chunks)
    uint32_t* Wk  = As + 2 * A_BUF;           // 2 x tf32 W buffers

    const int t      = threadIdx.x;
    const int lane   = t & 31;
    const int warp   = t >> 5;
    const int warp_m = warp >> 2;       // 0..1 -> 64 rows each
    const int warp_n = warp & 3;        // 0..3 -> 32 cols each
    const int row0   = blockIdx.x * 128;

#define CP_W(KC, BUF)                                                         \
    {                                                                         \
        const uint32_t* Wsrc_ =                                               \
            (((KC) < 4) ? g_wl_tf : g_wr_tf) + ((KC) & 3) * 32 * C;           \
        uint32_t* Wb_ = Wk + (BUF) * W_BUF;                                   \
        _Pragma("unroll")                                                     \
        for (int i = 0; i < 4; i++) {                                         \
            int f = t + i * 256;                                              \
            int kloc = f >> 5, n4 = f & 31;                                   \
            uint32_t dst = (uint32_t)__cvta_generic_to_shared(                \
                Wb_ + kloc * W_STRIDE + n4 * 4);                              \
            cp_async16(dst, Wsrc_ + kloc * C + n4 * 4);                       \
        }                                                                     \
        cp_async_commit();                                                    \
    }

    // ---- prologue: start W chunk 0 transfer, then gather ----
    CP_W(0, 0);

    // ================= Phase A: gather-aggregate into AggBf =================
    {
        const uint2* xb = (const uint2*)g_xbf;   // 8B = 4 bf16 per lane
        for (int i = 0; i < 16; i++) {
            int r    = warp * 16 + i;            // row within tile
            int grow = row0 + r;
            uint2 o  = make_uint2(0u, 0u);
            if (grow < NN) {
                int cnt = g_cnt[grow];
                int deg = min(cnt, CAP);
                const int* bkt = g_bucket + (size_t)grow * CAP;
                int i0 = (lane      < deg) ? __ldg(bkt + lane)      : 0;
                int i1 = (lane + 32 < deg) ? __ldg(bkt + lane + 32) : 0;
                int i2 = (lane + 64 < deg) ? __ldg(bkt + lane + 64) : 0;

                float4 acc = make_float4(0.f, 0.f, 0.f, 0.f);
                int j = 0;
                for (; j + 8 <= deg; j += 8) {
                    int s[8];
#pragma unroll
                    for (int u = 0; u < 8; u++) {
                        int jj = j + u;
                        int rr = (jj < 32) ? i0 : ((jj < 64) ? i1 : i2);
                        s[u] = __shfl_sync(0xffffffffu, rr, jj & 31);
                    }
                    uint2 v[8];
#pragma unroll
                    for (int u = 0; u < 8; u++)
                        v[u] = __ldg(xb + (size_t)s[u] * 32 + lane);
#pragma unroll
                    for (int u = 0; u < 8; u++)
                        acc_bf4(acc, v[u]);
                }
                for (; j < deg; j++) {
                    int rr = (j < 32) ? i0 : ((j < 64) ? i1 : i2);
                    int ss = __shfl_sync(0xffffffffu, rr, j & 31);
                    uint2 v = __ldg(xb + (size_t)ss * 32 + lane);
                    acc_bf4(acc, v);
                }
                float inv = 1.0f / fmaxf((float)cnt, 1.0f);
                __nv_bfloat162 h0 = __floats2bfloat162_rn(acc.x * inv, acc.y * inv);
                __nv_bfloat162 h1 = __floats2bfloat162_rn(acc.z * inv, acc.w * inv);
                o.x = *(uint32_t*)&h0;
                o.y = *(uint32_t*)&h1;
            }
            // AggBf[r][4*lane .. 4*lane+3] as two u32 words (u32 stride 68)
            *(uint2*)(Agg + r * 68 + 2 * lane) = o;
        }
    }

    cp_async_wait0();
    __syncthreads();     // agg tile + W chunk 0 visible to all warps

    // ================= Phase B: pipelined GEMM =================
    float acc[4][4][4];
#pragma unroll
    for (int mt = 0; mt < 4; mt++)
#pragma unroll
        for (int nt = 0; nt < 4; nt++)
#pragma unroll
            for (int j = 0; j < 4; j++) acc[mt][nt][j] = 0.f;

    float4 pa[4];     // fp32 x chunk prefetch

#define LOAD_X(KC)                                                            \
    {                                                                         \
        const int kb_ = ((KC) - 4) * 32;                                      \
        _Pragma("unroll")                                                     \
        for (int i = 0; i < 4; i++) {                                         \
            int f = t + i * 256;                                              \
            int r = f >> 3, c4 = f & 7;                                       \
            int grow = row0 + r;                                              \
            pa[i] = make_float4(0.f, 0.f, 0.f, 0.f);                          \
            if (grow < NN)                                                    \
                pa[i] = __ldg((const float4*)(x + (size_t)grow * C + kb_)     \
                              + c4);                                          \
        }                                                                     \
    }

#define STORE_X(KC)                                                           \
    {                                                                         \
        uint32_t* Ab_ = As + ((KC) & 1) * A_BUF;                              \
        _Pragma("unroll")                                                     \
        for (int i = 0; i < 4; i++) {                                         \
            int f = t + i * 256;                                              \
            int r = f >> 3, c4 = f & 7;                                       \
            uint4 u;                                                          \
            u.x = f2tf32(pa[i].x); u.y = f2tf32(pa[i].y);                     \
            u.z = f2tf32(pa[i].z); u.w = f2tf32(pa[i].w);                     \
            *(uint4*)(Ab_ + r * A_STRIDE + c4 * 4) = u;                       \
        }                                                                     \
    }

    const uint16_t* Ag16 = (const uint16_t*)Agg;

#pragma unroll
    for (int kc = 0; kc < 8; kc++) {
        if (kc < 7) CP_W(kc + 1, (kc + 1) & 1);
        if (kc >= 3 && kc < 7) LOAD_X(kc + 1);

        // ---- compute chunk kc ----
        const uint32_t* Wb = Wk + (kc & 1) * W_BUF;
#pragma unroll
        for (int ks = 0; ks < 4; ks++) {
            const int kk = ks * 8;
            uint32_t a[4][4], b[4][2];
            if (kc < 4) {
                // agg half: read bf16 smem, expand to tf32 (bit-exact)
                const int cb = kc * 32 + kk + (lane & 3);
#pragma unroll
                for (int mt = 0; mt < 4; mt++) {
                    int r = warp_m * 64 + mt * 16 + (lane >> 2);
                    a[mt][0] = ((uint32_t)Ag16[r * AGG_S16 + cb])       << 16;
                    a[mt][1] = ((uint32_t)Ag16[(r + 8) * AGG_S16 + cb]) << 16;
                    a[mt][2] = ((uint32_t)Ag16[r * AGG_S16 + cb + 4])   << 16;
                    a[mt][3] = ((uint32_t)Ag16[(r + 8) * AGG_S16 + cb + 4]) << 16;
                }
            } else {
                const uint32_t* Ab = As + (kc & 1) * A_BUF;
#pragma unroll
                for (int mt = 0; mt < 4; mt++) {
                    int r = warp_m * 64 + mt * 16 + (lane >> 2);
                    int c = kk + (lane & 3);
                    a[mt][0] = Ab[r * A_STRIDE + c];
                    a[mt][1] = Ab[(r + 8) * A_STRIDE + c];
                    a[mt][2] = Ab[r * A_STRIDE + c + 4];
                    a[mt][3] = Ab[(r + 8) * A_STRIDE + c + 4];
                }
            }
#pragma unroll
            for (int nt = 0; nt < 4; nt++) {
                int n  = warp_n * 32 + nt * 8 + (lane >> 2);
                int kr = kk + (lane & 3);
                b[nt][0] = Wb[kr * W_STRIDE + n];
                b[nt][1] = Wb[(kr + 4) * W_STRIDE + n];
            }
#pragma unroll
            for (int mt = 0; mt < 4; mt++)
#pragma unroll
                for (int nt = 0; nt < 4; nt++)
                    mma_tf32(acc[mt][nt], a[mt], b[nt]);
        }

        if (kc >= 3 && kc < 7) STORE_X(kc + 1);
        if (kc < 7) {
            cp_async_wait0();
            __syncthreads();
        }
    }

#undef CP_W
#undef LOAD_X
#undef STORE_X

    // ---- epilogue: bias + relu + float2 stores ----
#pragma unroll
    for (int nt = 0; nt < 4; nt++) {
        int c0 = warp_n * 32 + nt * 8 + 2 * (lane & 3);
        float2 bias = __ldg((const float2*)(b_l + c0));
#pragma unroll
        for (int mt = 0; mt < 4; mt++) {
            int r0 = row0 + warp_m * 64 + mt * 16 + (lane >> 2);
            if (r0 < NN) {
                float2 o;
                o.x = fmaxf(acc[mt][nt][0] + bias.x, 0.f);
                o.y = fmaxf(acc[mt][nt][1] + bias.y, 0.f);
                *(float2*)(out + (size_t)r0 * C + c0) = o;
            }
            int r1 = r0 + 8;
            if (r1 < NN) {
                float2 o;
                o.x = fmaxf(acc[mt][nt][2] + bias.x, 0.f);
                o.y = fmaxf(acc[mt][nt][3] + bias.y, 0.f);
                *(float2*)(out + (size_t)r1 * C + c0) = o;
            }
        }
    }
}

// ---------------------------------------------------------------------------
// Launch
// ---------------------------------------------------------------------------
extern "C" void kernel_launch(void* const* d_in, const int* in_sizes, int n_in,
                              void* d_out, int out_size)
{
    const float* x        = (const float*)d_in[0];
    const int*   edge_row = (const int*)d_in[1];
    const int*   edge_col = (const int*)d_in[2];
    const float* W_l      = (const float*)d_in[3];
    const float* b_l      = (const float*)d_in[4];
    const float* W_r      = (const float*)d_in[5];
    float*       out      = (float*)d_out;

    // 1) convert x -> bf16, W -> tf32 bits, zero counters
    {
        int n4 = NN * (C / 4);
        convert_kernel<<<(n4 + 255) / 256, 256>>>(x, W_l, W_r);
    }

    // 2) invert edge list into per-dst buckets
    fill_kernel<<<(EE + 255) / 256, 256>>>(edge_row, edge_col);

    // 3) fused gather + GEMM + epilogue (2 CTAs/SM)
    {
        const int smem_bytes = SMEM_U32 * sizeof(uint32_t);  // ~106.5 KB
        cudaFuncSetAttribute(sage_fused_kernel,
                             cudaFuncAttributeMaxDynamicSharedMemorySize,
                             smem_bytes);
        int blocks = (NN + 127) / 128;
        sage_fused_kernel<<<blocks, 256, smem_bytes>>>(x, b_l, out);
    }
}

// round 12
// speedup vs baseline: 1.2857x; 1.2857x over previous
#include <cuda_runtime.h>
#include <cuda_bf16.h>
#include <cstdint>

// Problem constants (fixed by the dataset)
#define NN 100000
#define EE 1600000
#define C  128           // IN_C == OUT_C == 128
#define KK2 256          // combined K = 2*C
#define CAP 96           // max bucket capacity per node (Poisson(16) tail ~1e-16)

// Scratch (no allocations allowed — device globals)
__device__ __nv_bfloat16 g_xbf[(size_t)NN * C];    // 25.6 MB bf16 copy of x (gather src)
__device__ int      g_cnt[NN];                     // per-node degree counters
__device__ int      g_bucket[(size_t)NN * CAP];    // 38.4 MB src-id buckets
__device__ uint32_t g_a_tf[(size_t)NN * KK2];      // 102.4 MB combined A: [agg | x] tf32
__device__ uint32_t g_w_tf[KK2 * C];               // combined W: [W_l ; W_r] tf32

// ---------------------------------------------------------------------------
// Helpers
// ---------------------------------------------------------------------------
__device__ __forceinline__ uint32_t f2tf32(float f) {
    uint32_t r;
    asm("cvt.rna.tf32.f32 %0, %1;" : "=r"(r) : "f"(f));
    return r;
}

__device__ __forceinline__ void mma_tf32(float c[4], const uint32_t a[4],
                                         const uint32_t b[2]) {
    asm volatile(
        "mma.sync.aligned.m16n8k8.row.col.f32.tf32.tf32.f32 "
        "{%0,%1,%2,%3}, {%4,%5,%6,%7}, {%8,%9}, {%0,%1,%2,%3};"
        : "+f"(c[0]), "+f"(c[1]), "+f"(c[2]), "+f"(c[3])
        : "r"(a[0]), "r"(a[1]), "r"(a[2]), "r"(a[3]), "r"(b[0]), "r"(b[1]));
}

// cp.async with optional zero-fill (src_size = 0 -> fill 16B of zeros)
__device__ __forceinline__ void cp_async16(uint32_t smem_addr, const void* gptr,
                                           int src_size) {
    asm volatile("cp.async.cg.shared.global [%0], [%1], 16, %2;"
                 :: "r"(smem_addr), "l"(gptr), "r"(src_size));
}
__device__ __forceinline__ void cp_async_commit() {
    asm volatile("cp.async.commit_group;");
}
__device__ __forceinline__ void cp_async_wait0() {
    asm volatile("cp.async.wait_group 0;");
}

__device__ __forceinline__ void acc_bf4(float4& acc, uint2 u) {
    acc.x += __uint_as_float(u.x << 16);
    acc.y += __uint_as_float(u.x & 0xFFFF0000u);
    acc.z += __uint_as_float(u.y << 16);
    acc.w += __uint_as_float(u.y & 0xFFFF0000u);
}

// ---------------------------------------------------------------------------
// Kernel 0: convert x -> bf16 (gather src) AND x -> tf32 into g_a_tf x-half;
//           W_l/W_r -> combined tf32 W; zero counters.
// ---------------------------------------------------------------------------
__global__ __launch_bounds__(256) void convert_kernel(
    const float* __restrict__ x,
    const float* __restrict__ W_l,
    const float* __restrict__ W_r)
{
    int i = blockIdx.x * blockDim.x + threadIdx.x;   // one float4 per thread
    const int n4 = NN * (C / 4);                      // 3.2M
    if (i < n4) {
        float4 v = __ldg((const float4*)x + i);
        // bf16 copy for the gather
        __nv_bfloat162 h0 = __floats2bfloat162_rn(v.x, v.y);
        __nv_bfloat162 h1 = __floats2bfloat162_rn(v.z, v.w);
        uint2 u;
        u.x = *(uint32_t*)&h0;
        u.y = *(uint32_t*)&h1;
        ((uint2*)g_xbf)[i] = u;
        // tf32 copy into the x-half of the combined A matrix
        int n  = i >> 5;          // node
        int c4 = i & 31;          // float4 within row
        uint4 t4;
        t4.x = f2tf32(v.x); t4.y = f2tf32(v.y);
        t4.z = f2tf32(v.z); t4.w = f2tf32(v.w);
        ((uint4*)g_a_tf)[(size_t)n * 64 + 32 + c4] = t4;   // row = 64 uint4
    }
    if (i < C * C / 4) {  // 4096 float4 per weight matrix
        int k  = i >> 5;
        int n4w = i & 31;
        float4 wl = __ldg((const float4*)W_l + i);
        float4 wr = __ldg((const float4*)W_r + i);
        uint4 ul, ur;
        ul.x = f2tf32(wl.x); ul.y = f2tf32(wl.y);
        ul.z = f2tf32(wl.z); ul.w = f2tf32(wl.w);
        ur.x = f2tf32(wr.x); ur.y = f2tf32(wr.y);
        ur.z = f2tf32(wr.z); ur.w = f2tf32(wr.w);
        ((uint4*)g_w_tf)[k * 32 + n4w]         = ul;   // rows 0-127: W_l
        ((uint4*)g_w_tf)[(128 + k) * 32 + n4w] = ur;   // rows 128-255: W_r
    }
    if (i < NN) g_cnt[i] = 0;
}

// ---------------------------------------------------------------------------
// Kernel 1: bucket fill. One thread per edge.
// ---------------------------------------------------------------------------
__global__ __launch_bounds__(256) void fill_kernel(
    const int* __restrict__ edge_row,   // dst
    const int* __restrict__ edge_col)   // src
{
    int e = blockIdx.x * blockDim.x + threadIdx.x;
    if (e >= EE) return;
    int d   = __ldg(edge_row + e);
    int s   = __ldg(edge_col + e);
    int pos = atomicAdd(g_cnt + d, 1);
    if (pos < CAP) {
        g_bucket[(size_t)d * CAP + pos] = s;
    }
}

// ---------------------------------------------------------------------------
// Kernel 2: gather-aggregate. One warp per node. Batch of 16 loads in flight
// (covers mean degree in one batch). Writes mean as tf32 into the agg-half
// of the combined A matrix.
// ---------------------------------------------------------------------------
__global__ __launch_bounds__(256) void gather_agg_kernel()
{
    int warp = (blockIdx.x * blockDim.x + threadIdx.x) >> 5;
    int lane = threadIdx.x & 31;
    if (warp >= NN) return;

    int cnt = g_cnt[warp];
    int deg = min(cnt, CAP);

    const int*   bkt = g_bucket + (size_t)warp * CAP;
    const uint2* xb  = (const uint2*)g_xbf;           // 8B = 4 bf16 per lane

    // Lane-parallel index preload (covers up to CAP=96)
    int i0 = (lane      < deg) ? __ldg(bkt + lane)      : 0;
    int i1 = (lane + 32 < deg) ? __ldg(bkt + lane + 32) : 0;
    int i2 = (lane + 64 < deg) ? __ldg(bkt + lane + 64) : 0;

    float4 acc = make_float4(0.f, 0.f, 0.f, 0.f);

    int j = 0;
    for (; j + 16 <= deg; j += 16) {
        int s[16];
#pragma unroll
        for (int u = 0; u < 16; u++) {
            int jj = j + u;
            int r  = (jj < 32) ? i0 : ((jj < 64) ? i1 : i2);
            s[u] = __shfl_sync(0xffffffffu, r, jj & 31);
        }
        uint2 v[16];
#pragma unroll
        for (int u = 0; u < 16; u++)
            v[u] = __ldg(xb + (size_t)s[u] * 32 + lane);
#pragma unroll
        for (int u = 0; u < 16; u++)
            acc_bf4(acc, v[u]);
    }
    for (; j + 4 <= deg; j += 4) {
        int s[4];
#pragma unroll
        for (int u = 0; u < 4; u++) {
            int jj = j + u;
            int r  = (jj < 32) ? i0 : ((jj < 64) ? i1 : i2);
            s[u] = __shfl_sync(0xffffffffu, r, jj & 31);
        }
        uint2 v[4];
#pragma unroll
        for (int u = 0; u < 4; u++)
            v[u] = __ldg(xb + (size_t)s[u] * 32 + lane);
#pragma unroll
        for (int u = 0; u < 4; u++)
            acc_bf4(acc, v[u]);
    }
    for (; j < deg; j++) {
        int r = (j < 32) ? i0 : ((j < 64) ? i1 : i2);
        int s = __shfl_sync(0xffffffffu, r, j & 31);
        uint2 v = __ldg(xb + (size_t)s * 32 + lane);
        acc_bf4(acc, v);
    }

    float inv = 1.0f / fmaxf((float)cnt, 1.0f);
    uint4 o;
    o.x = f2tf32(acc.x * inv);
    o.y = f2tf32(acc.y * inv);
    o.z = f2tf32(acc.z * inv);
    o.w = f2tf32(acc.w * inv);
    ((uint4*)g_a_tf)[(size_t)warp * 64 + lane] = o;    // agg-half (uint4 0..31)
}

// ---------------------------------------------------------------------------
// Kernel 3: lean pure-tf32 GEMM:  out = relu( A[N,256] @ W[256,128] + b )
// All operands pre-converted tf32 in globals; ALL staging via cp.async.
// CTA: 256 threads (8 warps, 2x4), CTA tile 64 rows x 128 cols, K in 8
// chunks of 32, double-buffered. Warp tile 32x32, acc 32 regs (~70 regs
// total) -> 3 CTAs/SM (24 warps) for latency hiding.
// A tile [r][k] stride 36 (bank 4a+q bijective), W tile [k][n] stride 136
// (bank 8q+a bijective).
// ---------------------------------------------------------------------------
#define A_STRIDE 36
#define W_STRIDE 136
#define A_BUF    (64 * A_STRIDE)      // u32 per buffer
#define W_BUF    (32 * W_STRIDE)
#define SMEM_U32 (2 * A_BUF + 2 * W_BUF)

__global__ __launch_bounds__(256, 3) void sage_gemm_kernel(
    const float* __restrict__ b_l,
    float*       __restrict__ out)
{
    extern __shared__ uint32_t sm[];
    uint32_t* As = sm;                 // 2 buffers
    uint32_t* Wk = sm + 2 * A_BUF;     // 2 buffers

    const int t      = threadIdx.x;
    const int lane   = t & 31;
    const int warp   = t >> 5;
    const int warp_m = warp >> 2;       // 0..1 -> 32 rows each
    const int warp_n = warp & 3;        // 0..3 -> 32 cols each
    const int row0   = blockIdx.x * 64;

    float acc[2][4][4];
#pragma unroll
    for (int mt = 0; mt < 2; mt++)
#pragma unroll
        for (int nt = 0; nt < 4; nt++)
#pragma unroll
            for (int j = 0; j < 4; j++) acc[mt][nt][j] = 0.f;

#define CP_CHUNK(KC, BUF)                                                     \
    {                                                                         \
        uint32_t* Ab_ = As + (BUF) * A_BUF;                                   \
        uint32_t* Wb_ = Wk + (BUF) * W_BUF;                                   \
        _Pragma("unroll")                                                     \
        for (int i = 0; i < 2; i++) {      /* A: 64 rows x 8 uint4 */         \
            int f = t + i * 256;                                              \
            int r = f >> 3, c4 = f & 7;                                       \
            int grow = row0 + r;                                              \
            uint32_t dst = (uint32_t)__cvta_generic_to_shared(                \
                Ab_ + r * A_STRIDE + c4 * 4);                                 \
            const uint32_t* src =                                             \
                g_a_tf + (size_t)grow * KK2 + (KC) * 32 + c4 * 4;             \
            cp_async16(dst, src, (grow < NN) ? 16 : 0);                       \
        }                                                                     \
        _Pragma("unroll")                                                     \
        for (int i = 0; i < 4; i++) {      /* W: 32 k x 32 uint4 */           \
            int f = t + i * 256;                                              \
            int kloc = f >> 5, n4 = f & 31;                                   \
            uint32_t dst = (uint32_t)__cvta_generic_to_shared(                \
                Wb_ + kloc * W_STRIDE + n4 * 4);                              \
            cp_async16(dst, g_w_tf + ((KC) * 32 + kloc) * C + n4 * 4, 16);    \
        }                                                                     \
        cp_async_commit();                                                    \
    }

    // Prologue: stage chunk 0 into buffer 0
    CP_CHUNK(0, 0);
    cp_async_wait0();
    __syncthreads();

#pragma unroll
    for (int kc = 0; kc < 8; kc++) {
        const int buf = kc & 1;
        if (kc < 7) CP_CHUNK(kc + 1, buf ^ 1);   // async into the other buffer

        // ---- compute chunk kc from buffer buf ----
        const uint32_t* Ab = As + buf * A_BUF;
        const uint32_t* Wb = Wk + buf * W_BUF;
#pragma unroll
        for (int ks = 0; ks < 4; ks++) {
            const int kk = ks * 8;
            uint32_t a[2][4], b[4][2];
#pragma unroll
            for (int mt = 0; mt < 2; mt++) {
                int r = warp_m * 32 + mt * 16 + (lane >> 2);
                int c = kk + (lane & 3);
                a[mt][0] = Ab[r * A_STRIDE + c];
                a[mt][1] = Ab[(r + 8) * A_STRIDE + c];
                a[mt][2] = Ab[r * A_STRIDE + c + 4];
                a[mt][3] = Ab[(r + 8) * A_STRIDE + c + 4];
            }
#pragma unroll
            for (int nt = 0; nt < 4; nt++) {
                int n  = warp_n * 32 + nt * 8 + (lane >> 2);
                int kr = kk + (lane & 3);
                b[nt][0] = Wb[kr * W_STRIDE + n];
                b[nt][1] = Wb[(kr + 4) * W_STRIDE + n];
            }
#pragma unroll
            for (int mt = 0; mt < 2; mt++)
#pragma unroll
                for (int nt = 0; nt < 4; nt++)
                    mma_tf32(acc[mt][nt], a[mt], b[nt]);
        }

        if (kc < 7) {
            cp_async_wait0();
            __syncthreads();
        }
    }

#undef CP_CHUNK

    // ---- epilogue: bias + relu + float2 stores ----
#pragma unroll
    for (int nt = 0; nt < 4; nt++) {
        int c0 = warp_n * 32 + nt * 8 + 2 * (lane & 3);
        float2 bias = __ldg((const float2*)(b_l + c0));
#pragma unroll
        for (int mt = 0; mt < 2; mt++) {
            int r0 = row0 + warp_m * 32 + mt * 16 + (lane >> 2);
            if (r0 < NN) {
                float2 o;
                o.x = fmaxf(acc[mt][nt][0] + bias.x, 0.f);
                o.y = fmaxf(acc[mt][nt][1] + bias.y, 0.f);
                *(float2*)(out + (size_t)r0 * C + c0) = o;
            }
            int r1 = r0 + 8;
            if (r1 < NN) {
                float2 o;
                o.x = fmaxf(acc[mt][nt][2] + bias.x, 0.f);
                o.y = fmaxf(acc[mt][nt][3] + bias.y, 0.f);
                *(float2*)(out + (size_t)r1 * C + c0) = o;
            }
        }
    }
}

// ---------------------------------------------------------------------------
// Launch
// ---------------------------------------------------------------------------
extern "C" void kernel_launch(void* const* d_in, const int* in_sizes, int n_in,
                              void* d_out, int out_size)
{
    const float* x        = (const float*)d_in[0];
    const int*   edge_row = (const int*)d_in[1];
    const int*   edge_col = (const int*)d_in[2];
    const float* W_l      = (const float*)d_in[3];
    const float* b_l      = (const float*)d_in[4];
    const float* W_r      = (const float*)d_in[5];
    float*       out      = (float*)d_out;

    // 1) convert x -> bf16 + tf32, W -> combined tf32, zero counters
    {
        int n4 = NN * (C / 4);
        convert_kernel<<<(n4 + 255) / 256, 256>>>(x, W_l, W_r);
    }

    // 2) invert edge list into per-dst buckets
    fill_kernel<<<(EE + 255) / 256, 256>>>(edge_row, edge_col);

    // 3) gather + mean-aggregate (one warp per node, MLP=16), writes tf32
    {
        int warps_per_block = 8;   // 256 threads
        int blocks = (NN + warps_per_block - 1) / warps_per_block;
        gather_agg_kernel<<<blocks, 256>>>();
    }

    // 4) lean pipelined tf32 GEMM + epilogue (3 CTAs/SM)
    {
        const int smem_bytes = SMEM_U32 * sizeof(uint32_t);  // ~52.5 KB
        cudaFuncSetAttribute(sage_gemm_kernel,
                             cudaFuncAttributeMaxDynamicSharedMemorySize,
                             smem_bytes);
        int blocks = (NN + 63) / 64;
        sage_gemm_kernel<<<blocks, 256, smem_bytes>>>(b_l, out);
    }
}